// round 1
// baseline (speedup 1.0000x reference)
#include <cuda_runtime.h>
#include <cstdint>
#include <cstddef>

// LIF scan, exact rounding emulation of (v - v*0.05f) + I per step.
// 4096 rows x 4096 steps. 128 CTAs x 1 warp, 32 rows per CTA.
// Inputs staged via cp.async double-buffered tiles; spikes staged in smem
// and written back coalesced. Chain-bound: ~16 cyc/step.

constexpr int Bn   = 4096;
constexpr int Ln   = 4096;
constexpr int TILE = 64;
constexpr int NT   = Ln / TILE;   // 64 tiles
constexpr int ROWS = 32;          // rows per CTA (one lane per row)
constexpr int STRIDE = 68;        // 64 + 4 pad floats -> conflict-free LDS/STS.128

__device__ __forceinline__ unsigned smem_addr(const void* p) {
    return (unsigned)__cvta_generic_to_shared(p);
}

__global__ void __launch_bounds__(32, 1)
lif_scan_kernel(const float* __restrict__ In, float* __restrict__ out) {
    __shared__ float s_in[2][ROWS][STRIDE];
    __shared__ float s_sp[ROWS][STRIDE];

    const int lane = threadIdx.x;           // 0..31, one row per lane
    const int row0 = blockIdx.x * ROWS;

    // tile copy mapping: 16 chunks; chunk k covers rows {2k, 2k+1}
    const int crow = lane >> 4;             // 0..1
    const int ccol = (lane & 15) * 4;       // float index of this lane's float4

    // prologue: prefetch tiles 0 and 1
    #pragma unroll
    for (int t = 0; t < 2; t++) {
        #pragma unroll
        for (int k = 0; k < 16; k++) {
            const int r = 2 * k + crow;
            const float* src = In + (size_t)(row0 + r) * Ln + t * TILE + ccol;
            unsigned dst = smem_addr(&s_in[t][r][ccol]);
            asm volatile("cp.async.cg.shared.global [%0], [%1], 16;" :: "r"(dst), "l"(src));
        }
        asm volatile("cp.async.commit_group;");
    }

    // State: w = pre-reset membrane potential of previous step, p = spike pred.
    // p=true initially => first step computes w = 0 + I_0 (v0 = 0).
    float w = 0.0f;
    bool  p = true;
    float cnt  = 0.0f;            // spike count (exact: < 2^24)
    float tsum = 0.0f;            // sum of spike times (exact: <= ~8.4M < 2^24)
    float latf = (float)Ln;       // first-spike index, Ln if none
    float tf   = 0.0f;            // running time as float (exact integers)
    const float BIG = (float)Ln;

    for (int tile = 0; tile < NT; tile++) {
        if (tile < NT - 1) asm volatile("cp.async.wait_group 1;" ::: "memory");
        else               asm volatile("cp.async.wait_group 0;" ::: "memory");
        __syncwarp();

        const float* inrow = &s_in[tile & 1][lane][0];
        float*       sprow = &s_sp[lane][0];

        #pragma unroll
        for (int j4 = 0; j4 < TILE / 4; j4++) {
            float4 iv = *reinterpret_cast<const float4*>(inrow + j4 * 4);
            float ivals[4] = {iv.x, iv.y, iv.z, iv.w};
            float svals[4];
            #pragma unroll
            for (int e = 0; e < 4; e++) {
                // exact emulation of: v_next = (v - v*0.05f) + I  (no FMA contraction)
                float qq = __fmul_rn(w, 0.05f);     // off-chain wrt p
                float uu = __fsub_rn(w, qq);
                float su = p ? 0.0f : uu;           // reset select (speculated)
                w = __fadd_rn(su, ivals[e]);
                p = (w >= 1.0f);
                float s = p ? 1.0f : 0.0f;          // forward spike value is exactly hard
                cnt += s;
                tsum = __fmaf_rn(s, tf, tsum);
                latf = fminf(latf, p ? tf : BIG);
                tf += 1.0f;
                svals[e] = s;
            }
            float4 sv;
            sv.x = svals[0]; sv.y = svals[1]; sv.z = svals[2]; sv.w = svals[3];
            *reinterpret_cast<float4*>(sprow + j4 * 4) = sv;
        }
        __syncwarp();

        // prefetch tile+2 into the buffer we just consumed
        if (tile + 2 < NT) {
            #pragma unroll
            for (int k = 0; k < 16; k++) {
                const int r = 2 * k + crow;
                const float* src = In + (size_t)(row0 + r) * Ln + (tile + 2) * TILE + ccol;
                unsigned dst = smem_addr(&s_in[tile & 1][r][ccol]);
                asm volatile("cp.async.cg.shared.global [%0], [%1], 16;" :: "r"(dst), "l"(src));
            }
            asm volatile("cp.async.commit_group;");
        }

        // coalesced write-back of the spike tile
        #pragma unroll
        for (int k = 0; k < 16; k++) {
            const int r = 2 * k + crow;
            float4 v = *reinterpret_cast<const float4*>(&s_sp[r][ccol]);
            *reinterpret_cast<float4*>(out + (size_t)(row0 + r) * Ln + tile * TILE + ccol) = v;
        }
        __syncwarp();
    }

    // tail outputs: [spikes (B*L)] [hard_latency (B)] [soft_latency (B)]
    const int row = row0 + lane;
    out[(size_t)Bn * Ln + row]      = latf;                      // == L if never fired
    out[(size_t)Bn * Ln + Bn + row] = tsum / (cnt + 1e-6f);      // spike-weighted mean time
}

extern "C" void kernel_launch(void* const* d_in, const int* in_sizes, int n_in,
                              void* d_out, int out_size) {
    (void)in_sizes; (void)n_in; (void)out_size;
    const float* In = (const float*)d_in[0];
    float* out = (float*)d_out;
    lif_scan_kernel<<<Bn / ROWS, 32>>>(In, out);
}